// round 2
// baseline (speedup 1.0000x reference)
#include <cuda_runtime.h>
#include <cuda_bf16.h>

#define SS   8
#define HH   544
#define WW   960
#define HID  64
#define BT   256
#define MAXP (BT * SS)

__global__ __launch_bounds__(BT)
void sky_kernel(const float* __restrict__ images,
                const float* __restrict__ extr,
                const float* __restrict__ intr,
                const float* __restrict__ W1,
                const float* __restrict__ b1,
                const float* __restrict__ W2,
                const float* __restrict__ b2,
                const float* __restrict__ pcd,
                const float* __restrict__ lsc,
                const int*   __restrict__ dsp,
                float* __restrict__ out, int N)
{
    __shared__ float sE[SS * 12];
    __shared__ float sK[SS * 9];
    __shared__ float sW1[3 * HID];
    __shared__ float sB1[HID];
    __shared__ float sW2[HID * 3];
    __shared__ float sB2[3];
    __shared__ float sX[BT], sY[BT], sZ[BT];
    __shared__ unsigned short sPair[MAXP];
    __shared__ float sC[MAXP * 3];
    __shared__ int  sWsum[BT / 32];

    const int tid = threadIdx.x;

    // decode downsample whether stored as int32 or float32 bits
    float ds;
    {
        int iv = *dsp;
        ds = (iv > 0 && iv < 1000000) ? (float)iv : __int_as_float(iv);
    }

    if (tid < SS * 12) sE[tid] = extr[(tid / 12) * 16 + (tid % 12)];
    if (tid < SS * 9) {
        int ij = tid % 9, i = ij / 3, j = ij % 3;
        float d = 1.0f;
        if (i == 0 && (j == 0 || j == 2)) d = ds;
        if (i == 1 && (j == 1 || j == 2)) d = ds;
        sK[tid] = intr[tid] / d;
    }
    if (tid < 3 * HID) sW1[tid] = W1[tid];
    if (tid < HID)     sB1[tid] = b1[tid];
    if (tid < HID * 3) sW2[tid] = W2[(tid / 3) * 6 + (tid % 3)];
    if (tid < 3)       sB2[tid] = b2[tid];

    const int n = blockIdx.x * BT + tid;
    const bool valid = (n < N);

    float X = 0.f, Y = 0.f, Z = 0.f;
    if (valid) {
        X = pcd[3 * n + 0];
        Y = pcd[3 * n + 1];
        Z = pcd[3 * n + 2];
    }
    sX[tid] = X; sY[tid] = Y; sZ[tid] = Z;
    __syncthreads();   // constants + XYZ visible

    // ---- Phase A: visibility mask per (point, cam) ----
    int mask = 0;
    if (valid) {
        #pragma unroll
        for (int s = 0; s < SS; ++s) {
            const float* E = sE + s * 12;
            const float* K = sK + s * 9;
            float c0 = E[0] * X + E[1]  * Y + E[2]  * Z + E[3];
            float c1 = E[4] * X + E[5]  * Y + E[6]  * Z + E[7];
            float c2 = E[8] * X + E[9]  * Y + E[10] * Z + E[11];
            float u = K[0] * c0 + K[1] * c1 + K[2] * c2;
            float v = K[3] * c0 + K[4] * c1 + K[5] * c2;
            float w = K[6] * c0 + K[7] * c1 + K[8] * c2;
            float zs = (fabsf(w) > 1e-6f) ? w : 1e-6f;
            float px = u / zs;
            float py = v / zs;
            bool m = (w > 0.001f) && (px >= 0.f) && (px <= (float)(WW - 1)) &&
                     (py >= 0.f) && (py <= (float)(HH - 1));
            if (m) mask |= (1 << s);
        }
    }

    // ---- Block-wide exclusive scan over popcounts (deterministic slots) ----
    const int pc   = __popc(mask);
    const int lane = tid & 31;
    const int wrp  = tid >> 5;
    int incl = pc;
    #pragma unroll
    for (int d = 1; d < 32; d <<= 1) {
        int v = __shfl_up_sync(0xffffffffu, incl, d);
        if (lane >= d) incl += v;
    }
    if (lane == 31) sWsum[wrp] = incl;
    __syncthreads();
    int base = 0, total = 0;
    #pragma unroll
    for (int k = 0; k < BT / 32; ++k) {
        int w = sWsum[k];
        if (k < wrp) base += w;
        total += w;
    }
    int slot = base + incl - pc;

    #pragma unroll
    for (int s = 0; s < SS; ++s) {
        if ((mask >> s) & 1) sPair[slot++] = (unsigned short)((tid << 3) | s);
    }
    __syncthreads();

    // ---- Phase B: compacted bilinear gather (full warps) ----
    for (int i = tid; i < total; i += BT) {
        const int e = sPair[i];
        const int p = e >> 3;
        const int s = e & 7;
        const float Xp = sX[p], Yp = sY[p], Zp = sZ[p];
        const float* E = sE + s * 12;
        const float* K = sK + s * 9;
        float c0 = E[0] * Xp + E[1]  * Yp + E[2]  * Zp + E[3];
        float c1 = E[4] * Xp + E[5]  * Yp + E[6]  * Zp + E[7];
        float c2 = E[8] * Xp + E[9]  * Yp + E[10] * Zp + E[11];
        float u = K[0] * c0 + K[1] * c1 + K[2] * c2;
        float v = K[3] * c0 + K[4] * c1 + K[5] * c2;
        float w = K[6] * c0 + K[7] * c1 + K[8] * c2;
        float zs = (fabsf(w) > 1e-6f) ? w : 1e-6f;
        float px = u / zs;
        float py = v / zs;

        int x0 = (int)floorf(px); x0 = min(max(x0, 0), WW - 2);
        int y0 = (int)floorf(py); y0 = min(max(y0, 0), HH - 2);
        float wx = px - (float)x0;
        float wy = py - (float)y0;
        float w00 = (1.f - wx) * (1.f - wy);
        float w01 = wx * (1.f - wy);
        float w10 = (1.f - wx) * wy;
        float w11 = wx * wy;

        const float* img = images + (size_t)s * 3 * HH * WW + (size_t)y0 * WW + x0;
        const float* pA = img;
        const float* pB = img + (size_t)HH * WW;
        const float* pC = img + (size_t)2 * HH * WW;
        // issue all 12 loads up front for MLP
        float a00 = __ldg(pA),          a01 = __ldg(pA + 1);
        float a10 = __ldg(pA + WW),     a11 = __ldg(pA + WW + 1);
        float b00 = __ldg(pB),          b01 = __ldg(pB + 1);
        float b10 = __ldg(pB + WW),     b11 = __ldg(pB + WW + 1);
        float g00 = __ldg(pC),          g01 = __ldg(pC + 1);
        float g10 = __ldg(pC + WW),     g11 = __ldg(pC + WW + 1);

        sC[3 * i + 0] = a00 * w00 + a01 * w01 + a10 * w10 + a11 * w11;
        sC[3 * i + 1] = b00 * w00 + b01 * w01 + b10 * w10 + b11 * w11;
        sC[3 * i + 2] = g00 * w00 + g01 * w01 + g10 * w10 + g11 * w11;
    }
    __syncthreads();

    // ---- Phase C: reduce, MLP, write ----
    if (!valid) return;

    float f0 = 0.f, f1 = 0.f, f2 = 0.f;
    const int off = base + incl - pc;   // recompute start slot for this point
    for (int k = 0; k < pc; ++k) {
        f0 += sC[3 * (off + k) + 0];
        f1 += sC[3 * (off + k) + 1];
        f2 += sC[3 * (off + k) + 2];
    }
    const float inv = 1.f / fmaxf((float)pc, 1.f);
    f0 *= inv; f1 *= inv; f2 *= inv;

    float a0 = sB2[0], a1 = sB2[1], a2 = sB2[2];
    #pragma unroll
    for (int j = 0; j < HID; ++j) {
        float h = f0 * sW1[j] + f1 * sW1[HID + j] + f2 * sW1[2 * HID + j] + sB1[j];
        h = fmaxf(h, 0.f);
        a0 = fmaf(h, sW2[j * 3 + 0], a0);
        a1 = fmaf(h, sW2[j * 3 + 1], a1);
        a2 = fmaf(h, sW2[j * 3 + 2], a2);
    }

    const float pm = (pc > 0) ? 1.f : 0.f;
    float* op = out + (size_t)6 * n;
    op[0] = tanhf(a0) * pm;
    op[1] = tanhf(a1) * pm;
    op[2] = tanhf(a2) * pm;
    op[3] = expf(lsc[3 * n + 0]) * pm;
    op[4] = expf(lsc[3 * n + 1]) * pm;
    op[5] = expf(lsc[3 * n + 2]) * pm;
}

extern "C" void kernel_launch(void* const* d_in, const int* in_sizes, int n_in,
                              void* d_out, int out_size)
{
    const float* images = (const float*)d_in[0];
    const float* extr   = (const float*)d_in[1];
    const float* intr   = (const float*)d_in[2];
    const float* W1     = (const float*)d_in[3];
    const float* b1     = (const float*)d_in[4];
    const float* W2     = (const float*)d_in[5];
    const float* b2     = (const float*)d_in[6];
    const float* pcd    = (const float*)d_in[7];
    const float* lsc    = (const float*)d_in[8];
    const int*   dsp    = (const int*)  d_in[9];

    int N = in_sizes[7] / 3;
    int blocks = (N + BT - 1) / BT;
    sky_kernel<<<blocks, BT>>>(images, extr, intr, W1, b1, W2, b2,
                               pcd, lsc, dsp, (float*)d_out, N);
}

// round 4
// speedup vs baseline: 1.5111x; 1.5111x over previous
#include <cuda_runtime.h>
#include <cuda_bf16.h>

#define SS   8
#define HH   544
#define WW   960
#define HID  64

__global__ __launch_bounds__(256)
void sky_kernel(const float* __restrict__ images,
                const float* __restrict__ extr,
                const float* __restrict__ intr,
                const float* __restrict__ W1,
                const float* __restrict__ b1,
                const float* __restrict__ W2,
                const float* __restrict__ b2,
                const float* __restrict__ pcd,
                const float* __restrict__ lsc,
                const int*   __restrict__ dsp,
                float* __restrict__ out, int N)
{
    __shared__ float sE[SS * 12];    // extrinsics rows 0..2 (3x4 each)
    __shared__ float sK[SS * 9];     // Ks = intrinsics / D
    __shared__ float sW1[3 * HID];   // (3,64) row-major
    __shared__ float sB1[HID];
    __shared__ float sW2[HID * 3];   // only first 3 output cols used (rgb)
    __shared__ float sB2[3];

    const int tid = threadIdx.x;

    // decode downsample whether stored as int32 or float32 bits
    float ds;
    {
        int iv = *dsp;
        ds = (iv > 0 && iv < 1000000) ? (float)iv : __int_as_float(iv);
    }

    if (tid < SS * 12) sE[tid] = extr[(tid / 12) * 16 + (tid % 12)];
    if (tid < SS * 9) {
        int ij = tid % 9, i = ij / 3, j = ij % 3;
        float d = 1.0f;
        if (i == 0 && (j == 0 || j == 2)) d = ds;
        if (i == 1 && (j == 1 || j == 2)) d = ds;
        sK[tid] = intr[tid] / d;
    }
    if (tid < 3 * HID) sW1[tid] = W1[tid];
    if (tid < HID)     sB1[tid] = b1[tid];
    if (tid < HID * 3) sW2[tid] = W2[(tid / 3) * 6 + (tid % 3)];
    if (tid < 3)       sB2[tid] = b2[tid];
    __syncthreads();

    const int n = blockIdx.x * blockDim.x + tid;
    if (n >= N) return;

    const float X = pcd[3 * n + 0];
    const float Y = pcd[3 * n + 1];
    const float Z = pcd[3 * n + 2];

    float f0 = 0.f, f1 = 0.f, f2 = 0.f, cnt = 0.f;

    #pragma unroll
    for (int s = 0; s < SS; ++s) {
        const float* E = sE + s * 12;
        const float* K = sK + s * 9;
        // cam = E[:3,:4] @ [X,Y,Z,1]   (same op order as reference)
        float c0 = E[0] * X + E[1]  * Y + E[2]  * Z + E[3];
        float c1 = E[4] * X + E[5]  * Y + E[6]  * Z + E[7];
        float c2 = E[8] * X + E[9]  * Y + E[10] * Z + E[11];
        // uv = Ks @ cam
        float u = K[0] * c0 + K[1] * c1 + K[2] * c2;
        float v = K[3] * c0 + K[4] * c1 + K[5] * c2;
        float w = K[6] * c0 + K[7] * c1 + K[8] * c2;
        float zs = (fabsf(w) > 1e-6f) ? w : 1e-6f;
        float px = u / zs;
        float py = v / zs;
        bool m = (w > 0.001f) && (px >= 0.f) && (px <= (float)(WW - 1)) &&
                 (py >= 0.f) && (py <= (float)(HH - 1));
        if (m) {
            int x0 = (int)floorf(px); x0 = min(max(x0, 0), WW - 2);
            int y0 = (int)floorf(py); y0 = min(max(y0, 0), HH - 2);
            float wx = px - (float)x0;
            float wy = py - (float)y0;
            float w00 = (1.f - wx) * (1.f - wy);
            float w01 = wx * (1.f - wy);
            float w10 = (1.f - wx) * wy;
            float w11 = wx * wy;
            const float* img = images + (size_t)s * 3 * HH * WW + (size_t)y0 * WW + x0;
            {
                const float* p = img;
                f0 += p[0] * w00 + p[1] * w01 + p[WW] * w10 + p[WW + 1] * w11;
            }
            {
                const float* p = img + (size_t)HH * WW;
                f1 += p[0] * w00 + p[1] * w01 + p[WW] * w10 + p[WW + 1] * w11;
            }
            {
                const float* p = img + (size_t)2 * HH * WW;
                f2 += p[0] * w00 + p[1] * w01 + p[WW] * w10 + p[WW + 1] * w11;
            }
            cnt += 1.f;
        }
    }

    float* op = out + (size_t)6 * n;

    // ---- Invisible point: reference multiplies everything by proj_mask=0.
    //      Skip MLP / tanh / exp / lsc loads entirely; write six zeros. ----
    if (cnt == 0.f) {
        op[0] = 0.f; op[1] = 0.f; op[2] = 0.f;
        op[3] = 0.f; op[4] = 0.f; op[5] = 0.f;
        return;
    }

    const float inv = 1.f / cnt;   // cnt >= 1 here, matches fmax(cnt,1)
    f0 *= inv; f1 *= inv; f2 *= inv;

    // MLP: h = relu(feat @ W1 + b1); rgb = tanh(h @ W2[:, :3] + b2[:3])
    float a0 = sB2[0], a1 = sB2[1], a2 = sB2[2];
    #pragma unroll
    for (int j = 0; j < HID; ++j) {
        float h = f0 * sW1[j] + f1 * sW1[HID + j] + f2 * sW1[2 * HID + j] + sB1[j];
        h = fmaxf(h, 0.f);
        a0 = fmaf(h, sW2[j * 3 + 0], a0);
        a1 = fmaf(h, sW2[j * 3 + 1], a1);
        a2 = fmaf(h, sW2[j * 3 + 2], a2);
    }

    op[0] = tanhf(a0);
    op[1] = tanhf(a1);
    op[2] = tanhf(a2);
    op[3] = __expf(lsc[3 * n + 0]);
    op[4] = __expf(lsc[3 * n + 1]);
    op[5] = __expf(lsc[3 * n + 2]);
}

extern "C" void kernel_launch(void* const* d_in, const int* in_sizes, int n_in,
                              void* d_out, int out_size)
{
    const float* images = (const float*)d_in[0];
    const float* extr   = (const float*)d_in[1];
    const float* intr   = (const float*)d_in[2];
    const float* W1     = (const float*)d_in[3];
    const float* b1     = (const float*)d_in[4];
    const float* W2     = (const float*)d_in[5];
    const float* b2     = (const float*)d_in[6];
    const float* pcd    = (const float*)d_in[7];
    const float* lsc    = (const float*)d_in[8];
    const int*   dsp    = (const int*)  d_in[9];

    int N = in_sizes[7] / 3;
    int threads = 256;
    int blocks = (N + threads - 1) / threads;
    sky_kernel<<<blocks, threads>>>(images, extr, intr, W1, b1, W2, b2,
                                    pcd, lsc, dsp, (float*)d_out, N);
}

// round 5
// speedup vs baseline: 1.6036x; 1.0612x over previous
#include <cuda_runtime.h>
#include <cuda_bf16.h>

#define SS   8
#define HH   544
#define WW   960
#define HID  64
#define BT   256

__global__ __launch_bounds__(BT)
void sky_kernel(const float* __restrict__ images,
                const float* __restrict__ extr,
                const float* __restrict__ intr,
                const float* __restrict__ W1,
                const float* __restrict__ b1,
                const float* __restrict__ W2,
                const float* __restrict__ b2,
                const float* __restrict__ pcd,
                const float* __restrict__ lsc,
                const int*   __restrict__ dsp,
                float* __restrict__ out, int N, int NW, int PERM)
{
    __shared__ float sE[SS * 12];
    __shared__ float sK[SS * 9];
    __shared__ float sW1[3 * HID];
    __shared__ float sB1[HID];
    __shared__ float sW2[HID * 3];
    __shared__ float sB2[3];

    const int tid = threadIdx.x;

    float ds;
    {
        int iv = *dsp;
        ds = (iv > 0 && iv < 1000000) ? (float)iv : __int_as_float(iv);
    }

    if (tid < SS * 12) sE[tid] = extr[(tid / 12) * 16 + (tid % 12)];
    if (tid < SS * 9) {
        int ij = tid % 9, i = ij / 3, j = ij % 3;
        float d = 1.0f;
        if (i == 0 && (j == 0 || j == 2)) d = ds;
        if (i == 1 && (j == 1 || j == 2)) d = ds;
        sK[tid] = intr[tid] / d;
    }
    if (tid < 3 * HID) sW1[tid] = W1[tid];
    if (tid < HID)     sB1[tid] = b1[tid];
    if (tid < HID * 3) sW2[tid] = W2[(tid / 3) * 6 + (tid % 3)];
    if (tid < 3)       sB2[tid] = b2[tid];
    __syncthreads();

    // ---- warp-granularity work scatter: balance heavy/light warps across SMs.
    //      Within a warp points stay consecutive (coalesced pcd/lsc/out). ----
    const int gwarp = (blockIdx.x * BT + tid) >> 5;
    if (gwarp >= NW) return;
    const long long pw = ((long long)gwarp * PERM) % NW;
    const int n = (int)(pw << 5) + (tid & 31);
    if (n >= N) return;

    const float X = pcd[3 * n + 0];
    const float Y = pcd[3 * n + 1];
    const float Z = pcd[3 * n + 2];

    float f0 = 0.f, f1 = 0.f, f2 = 0.f, cnt = 0.f;

    #pragma unroll
    for (int s = 0; s < SS; ++s) {
        const float* E = sE + s * 12;
        const float* K = sK + s * 9;
        float c0 = E[0] * X + E[1]  * Y + E[2]  * Z + E[3];
        float c1 = E[4] * X + E[5]  * Y + E[6]  * Z + E[7];
        float c2 = E[8] * X + E[9]  * Y + E[10] * Z + E[11];
        float u = K[0] * c0 + K[1] * c1 + K[2] * c2;
        float v = K[3] * c0 + K[4] * c1 + K[5] * c2;
        float w = K[6] * c0 + K[7] * c1 + K[8] * c2;
        float zs = (fabsf(w) > 1e-6f) ? w : 1e-6f;
        float px = u / zs;
        float py = v / zs;
        bool m = (w > 0.001f) && (px >= 0.f) && (px <= (float)(WW - 1)) &&
                 (py >= 0.f) && (py <= (float)(HH - 1));
        if (m) {
            int x0 = (int)floorf(px); x0 = min(max(x0, 0), WW - 2);
            int y0 = (int)floorf(py); y0 = min(max(y0, 0), HH - 2);
            float wx = px - (float)x0;
            float wy = py - (float)y0;
            float w00 = (1.f - wx) * (1.f - wy);
            float w01 = wx * (1.f - wy);
            float w10 = (1.f - wx) * wy;
            float w11 = wx * wy;
            const float* img = images + (size_t)s * 3 * HH * WW + (size_t)y0 * WW + x0;
            {
                const float* p = img;
                f0 += p[0] * w00 + p[1] * w01 + p[WW] * w10 + p[WW + 1] * w11;
            }
            {
                const float* p = img + (size_t)HH * WW;
                f1 += p[0] * w00 + p[1] * w01 + p[WW] * w10 + p[WW + 1] * w11;
            }
            {
                const float* p = img + (size_t)2 * HH * WW;
                f2 += p[0] * w00 + p[1] * w01 + p[WW] * w10 + p[WW + 1] * w11;
            }
            cnt += 1.f;
        }
    }

    float2* op = (float2*)(out + (size_t)6 * n);   // 24B offset -> 8B aligned

    if (cnt == 0.f) {
        op[0] = make_float2(0.f, 0.f);
        op[1] = make_float2(0.f, 0.f);
        op[2] = make_float2(0.f, 0.f);
        return;
    }

    const float inv = 1.f / cnt;
    f0 *= inv; f1 *= inv; f2 *= inv;

    float a0 = sB2[0], a1 = sB2[1], a2 = sB2[2];
    #pragma unroll
    for (int j = 0; j < HID; ++j) {
        float h = f0 * sW1[j] + f1 * sW1[HID + j] + f2 * sW1[2 * HID + j] + sB1[j];
        h = fmaxf(h, 0.f);
        a0 = fmaf(h, sW2[j * 3 + 0], a0);
        a1 = fmaf(h, sW2[j * 3 + 1], a1);
        a2 = fmaf(h, sW2[j * 3 + 2], a2);
    }

    op[0] = make_float2(tanhf(a0), tanhf(a1));
    op[1] = make_float2(tanhf(a2), __expf(lsc[3 * n + 0]));
    op[2] = make_float2(__expf(lsc[3 * n + 1]), __expf(lsc[3 * n + 2]));
}

extern "C" void kernel_launch(void* const* d_in, const int* in_sizes, int n_in,
                              void* d_out, int out_size)
{
    const float* images = (const float*)d_in[0];
    const float* extr   = (const float*)d_in[1];
    const float* intr   = (const float*)d_in[2];
    const float* W1     = (const float*)d_in[3];
    const float* b1     = (const float*)d_in[4];
    const float* W2     = (const float*)d_in[5];
    const float* b2     = (const float*)d_in[6];
    const float* pcd    = (const float*)d_in[7];
    const float* lsc    = (const float*)d_in[8];
    const int*   dsp    = (const int*)  d_in[9];

    int N  = in_sizes[7] / 3;
    int NW = (N + 31) / 32;

    // permutation multiplier ~ golden-ratio * NW, coprime to NW
    int PERM = (int)(0.6180339887 * NW) | 1;
    while (true) {
        int a = PERM, b = NW;
        while (b) { int t = a % b; a = b; b = t; }
        if (a == 1) break;
        PERM += 2;
    }

    int blocks = (NW * 32 + BT - 1) / BT;
    sky_kernel<<<blocks, BT>>>(images, extr, intr, W1, b1, W2, b2,
                               pcd, lsc, dsp, (float*)d_out, N, NW, PERM);
}